// round 8
// baseline (speedup 1.0000x reference)
#include <cuda_runtime.h>

#define CHN   4
#define HHT   128
#define WWD   128
#define TT    50
#define TP    52          // padded t-stride: mult of 4 (LDS.128), conflict-free
#define SOP   51          // staging row stride: gcd(51,32)=1 -> conflict-free
#define NBATCH 8
#define NPIX  (NBATCH*CHN*HHT*WWD)
#define NELEM (NPIX*TT)

__device__ float g_bufA[NELEM];
__device__ float g_bufB[NELEM];

typedef unsigned long long u64;

// Pre-DUPLICATED weights in CONSTANT memory: zero packing instructions at use.
// c_w5d[tap*2+0] = (w0,w0,w1,w1), [tap*2+1] = (w2,w2,w3,w3), tap=(ci*K+kh)*K+kw
__constant__ ulonglong2 c_w5d[200];
__constant__ ulonglong2 c_w3d[72];
__device__ float4 g_wpack[272];   // staging for memcpy-to-symbol

template <int K>
__device__ __forceinline__ ulonglong2 cwload(int i);
template <>
__device__ __forceinline__ ulonglong2 cwload<5>(int i) { return c_w5d[i]; }
template <>
__device__ __forceinline__ ulonglong2 cwload<3>(int i) { return c_w3d[i]; }

__device__ __forceinline__ void fma2(u64& d, u64 a, u64 b) {
    asm("fma.rn.f32x2 %0, %1, %2, %0;" : "+l"(d) : "l"(a), "l"(b));
}
__device__ __forceinline__ float2 upk(u64 v) {
    float2 f;
    f.x = __uint_as_float((unsigned)(v & 0xffffffffull));
    f.y = __uint_as_float((unsigned)(v >> 32));
    return f;
}

// Repack OIHW -> duplicated-pair float4 staging, then D2D to constant.
__global__ void repack_kernel(const float* __restrict__ w1,
                              const float* __restrict__ w2) {
    int tid = threadIdx.x;
    if (tid < 100) {   // conv5 taps
        float a = w1[tid], b = w1[100 + tid], c = w1[200 + tid], d = w1[300 + tid];
        g_wpack[tid * 2 + 0] = make_float4(a, a, b, b);
        g_wpack[tid * 2 + 1] = make_float4(c, c, d, d);
    }
    if (tid >= 128 && tid < 164) {   // conv3 taps
        int t = tid - 128;
        float a = w2[t], b = w2[36 + t], c = w2[72 + t], d = w2[108 + t];
        g_wpack[200 + t * 2 + 0] = make_float4(a, a, b, b);
        g_wpack[200 + t * 2 + 1] = make_float4(c, c, d, d);
    }
}

// ---------------------------------------------------------------------------
// Standalone alpha-PSP (layer 1). Warp-local smem transpose. (39us, near-roof)
// ---------------------------------------------------------------------------
#define PW_PAD 53
#define PW_WARPS 8
#define PW_SMEM (PW_WARPS * 32 * PW_PAD * 4)

__global__ void __launch_bounds__(256, 4) psp_kernel(const float* __restrict__ in,
                                                     float* __restrict__ out,
                                                     float r, float coef) {
    extern __shared__ float sm[];
    const int lane = threadIdx.x & 31;
    const int wrp  = threadIdx.x >> 5;
    float* ws = sm + wrp * 32 * PW_PAD;
    const long base = (long)(blockIdx.x * (PW_WARPS * 32) + wrp * 32) * TT;
    const float* g = in + base;
#pragma unroll
    for (int w = 0; w < 32; ++w) {
        ws[w * PW_PAD + lane] = g[w * TT + lane];
        if (lane < TT - 32) ws[w * PW_PAD + 32 + lane] = g[w * TT + 32 + lane];
    }
    __syncwarp();
    float* row = ws + lane * PW_PAD;
    float s1 = 0.f, s2 = 0.f;
#pragma unroll
    for (int t = 0; t < TT; ++t) {
        float x = row[t];
        row[t] = coef * s2;
        s1 = fmaf(r, s1, x);
        s2 = fmaf(r, s2, r * s1);
    }
    __syncwarp();
    float* o = out + base;
#pragma unroll
    for (int w = 0; w < 32; ++w) {
        o[w * TT + lane] = ws[w * PW_PAD + lane];
        if (lane < TT - 32) o[w * TT + 32 + lane] = ws[w * PW_PAD + 32 + lane];
    }
}

// ---------------------------------------------------------------------------
// Fused conv(KxK, 4->4, pad K/2) + spike epilogue.
// Block (32w, h, n), 416 thr = 13 warps, thread = (w=lane, t-quad t0=4*wrp).
// Per tap: 1 LDS.128 input + 2 LDC.128 duplicated weights + 8 FFMA2. Zero ALU.
// Fill & store fully structured (no div/mod).
// ---------------------------------------------------------------------------
template <int K, int CIH, int EPI>
__global__ void __launch_bounds__(416, 3)
conv_fused_kernel(const float* __restrict__ in, float* __restrict__ out,
                  float rR, float cR, float theta, float rP, float cP) {
    constexpr int PAD = K / 2;
    constexpr int WH  = 32 + 2 * PAD;
    constexpr int SIN = CIH * K * WH * TP;

    extern __shared__ float sm[];
    float* s_in = sm;

    const int tid  = threadIdx.x;
    const int lane = tid & 31;
    const int wrp  = tid >> 5;
    const int w0   = blockIdx.x * 32;
    const int h    = blockIdx.y;
    const int n    = blockIdx.z;
    const int t0   = wrp * 4;

    u64 acc[4][2];   // [co][(t0,t0+1)|(t0+2,t0+3)]
#pragma unroll
    for (int c = 0; c < 4; ++c) { acc[c][0] = 0ull; acc[c][1] = 0ull; }

#pragma unroll
    for (int cib = 0; cib < CHN; cib += CIH) {
        if (cib) __syncthreads();
        // structured fill: unrolled (ci,kh), row += 13 -> pure address adds
        for (int ci = 0; ci < CIH; ++ci) {
#pragma unroll
            for (int kh = 0; kh < K; ++kh) {
                const int hh  = h + kh - PAD;
                const bool hok = (hh >= 0) && (hh < HHT);
                const float* src = in + (((long)(n * CHN + cib + ci) * HHT + hh) * WWD + (w0 - PAD)) * TT;
                float* dst = s_in + (ci * K + kh) * WH * TP;
                for (int row = wrp; row < WH; row += 13) {
                    const int wg = w0 - PAD + row;
                    const bool ok = hok && (wg >= 0) && (wg < WWD);
                    float v0 = 0.f, v1 = 0.f;
                    if (ok) {
                        v0 = src[row * TT + lane];
                        if (lane < TT - 32) v1 = src[row * TT + 32 + lane];
                    }
                    dst[row * TP + lane] = v0;
                    if (lane < TT - 32) dst[row * TP + 32 + lane] = v1;
                }
            }
        }
        __syncthreads();
        // compute: LDS.128 input + 2x LDC.128 duplicated weights + FFMA2
#pragma unroll
        for (int ci = 0; ci < CIH; ++ci) {
#pragma unroll
            for (int kh = 0; kh < K; ++kh) {
                const float* rowp = s_in + ((ci * K + kh) * WH + lane) * TP + t0;
#pragma unroll
                for (int kw = 0; kw < K; ++kw) {
                    const int tap = ((cib + ci) * K + kh) * K + kw;
                    const ulonglong2 iv = *reinterpret_cast<const ulonglong2*>(rowp + kw * TP);
                    const ulonglong2 wa = cwload<K>(tap * 2);
                    const ulonglong2 wb = cwload<K>(tap * 2 + 1);
                    fma2(acc[0][0], iv.x, wa.x);
                    fma2(acc[0][1], iv.y, wa.x);
                    fma2(acc[1][0], iv.x, wa.y);
                    fma2(acc[1][1], iv.y, wa.y);
                    fma2(acc[2][0], iv.x, wb.x);
                    fma2(acc[2][1], iv.y, wb.x);
                    fma2(acc[3][0], iv.x, wb.y);
                    fma2(acc[3][1], iv.y, wb.y);
                }
            }
        }
    }
    __syncthreads();

    // stage conv results: s_out[co][w][SOP]
    float* s_out = sm;   // overlay: 4*32*51 floats < SIN
#pragma unroll
    for (int co = 0; co < 4; ++co) {
        float* p = s_out + co * (32 * SOP) + lane * SOP + t0;
        float2 a = upk(acc[co][0]);
        float2 b = upk(acc[co][1]);
        p[0] = a.x;
        p[1] = a.y;
        if (t0 + 2 < TT) p[2] = b.x;
        if (t0 + 3 < TT) p[3] = b.y;
    }
    __syncthreads();

    // fused spike-dynamics epilogue: 128 pixels (4co x 32w)
    if (tid < 128) {
        const int co = tid >> 5;
        const int w  = tid & 31;
        float* row = s_out + co * (32 * SOP) + w * SOP;
        float sd1 = 0.f, sd2 = 0.f, sp1 = 0.f, sp2 = 0.f;
#pragma unroll
        for (int t = 0; t < TT; ++t) {
            float m = fmaf(cR, sd2, row[t]);
            float s = (m >= theta) ? 1.f : 0.f;
            sd1 = fmaf(rR, sd1, s);
            sd2 = fmaf(rR, sd2, rR * sd1);
            if (EPI == 0) {
                row[t] = cP * sp2;
                sp1 = fmaf(rP, sp1, s);
                sp2 = fmaf(rP, sp2, rP * sp1);
            } else {
                row[t] = s;
            }
        }
    }
    __syncthreads();

    // structured coalesced store: warp-per-w-row, no division
#pragma unroll
    for (int co = 0; co < 4; ++co) {
        const float* sbase = s_out + co * (32 * SOP);
        float* gbase = out + (((long)(n * CHN + co) * HHT + h) * WWD + w0) * TT;
        for (int w = wrp; w < 32; w += 13) {
            const float* srow = sbase + w * SOP;
            float* grow = gbase + w * TT;
            grow[lane] = srow[lane];
            if (lane < TT - 32) grow[32 + lane] = srow[32 + lane];
        }
    }
}

// ---------------------------------------------------------------------------

extern "C" void kernel_launch(void* const* d_in, const int* in_sizes, int n_in,
                              void* d_out, int out_size) {
    const float* x  = (const float*)d_in[0];
    const float* w1 = (const float*)d_in[1];
    const float* w2 = (const float*)d_in[2];
    float* outp = (float*)d_out;

    float *bufA, *bufB;
    cudaGetSymbolAddress((void**)&bufA, g_bufA);
    cudaGetSymbolAddress((void**)&bufB, g_bufB);
    float4* wpack;
    cudaGetSymbolAddress((void**)&wpack, g_wpack);

    const int SMEM5 = 1 * 5 * 36 * TP * 4;   // 37440 B -> 3 blocks/SM
    const int SMEM3 = 2 * 3 * 34 * TP * 4;   // 42432 B -> 3 blocks/SM
    cudaFuncSetAttribute((const void*)conv_fused_kernel<5, 1, 0>,
                         cudaFuncAttributeMaxDynamicSharedMemorySize, SMEM5);
    cudaFuncSetAttribute((const void*)conv_fused_kernel<3, 2, 1>,
                         cudaFuncAttributeMaxDynamicSharedMemorySize, SMEM3);
    cudaFuncSetAttribute((const void*)psp_kernel,
                         cudaFuncAttributeMaxDynamicSharedMemorySize, PW_SMEM);

    const float r1  = (float)0.36787944117144233;   // exp(-1/tau1)
    const float cP1 = (float)2.718281828459045;     // e/tau1
    const float rR1 = (float)0.36787944117144233;   // exp(-1/tauRef1)
    const float cR1 = (float)(-54.365636569180902); // -scaleRef*theta1*e/tauRef1
    const float th1 = 20.0f;
    const float r2  = (float)0.6065306597126334;    // exp(-1/tau2)
    const float cP2 = (float)1.3591409142295225;    // e/tau2
    const float rR2 = (float)0.6065306597126334;    // exp(-1/tauRef2)
    const float cR2 = (float)(-54.365636569180902); // -scaleRef*theta2*e/tauRef2
    const float th2 = 40.0f;

    const int PGRID = NPIX / (PW_WARPS * 32);   // 2048
    dim3 cgrid(WWD / 32, HHT, NBATCH);          // (4,128,8)

    repack_kernel<<<1, 256>>>(w1, w2);
    cudaMemcpyToSymbolAsync(c_w5d, wpack, 200 * sizeof(float4), 0,
                            cudaMemcpyDeviceToDevice, 0);
    cudaMemcpyToSymbolAsync(c_w3d, wpack + 200, 72 * sizeof(float4), 0,
                            cudaMemcpyDeviceToDevice, 0);

    psp_kernel<<<PGRID, 256, PW_SMEM>>>(x, bufA, r1, cP1);
    conv_fused_kernel<5, 1, 0><<<cgrid, 416, SMEM5>>>(bufA, bufB,
                                                      rR1, cR1, th1, r2, cP2);
    conv_fused_kernel<3, 2, 1><<<cgrid, 416, SMEM3>>>(bufB, outp,
                                                      rR2, cR2, th2, 0.f, 0.f);
}

// round 9
// speedup vs baseline: 1.1740x; 1.1740x over previous
#include <cuda_runtime.h>

#define CHN   4
#define HHT   128
#define WWD   128
#define TT    50
#define TP    52          // padded t-stride: mult of 4 (LDS.128), conflict-free
#define SOP   52          // staging row stride (floats), float2 aligned
#define NBATCH 8
#define NPIX  (NBATCH*CHN*HHT*WWD)
#define NELEM (NPIX*TT)

__device__ float g_bufA[NELEM];
__device__ float g_bufB[NELEM];

typedef unsigned long long u64;

// Pre-duplicated weights in constant memory.
// c_w5d[tap*2+0]=(w0,w0,w1,w1), [tap*2+1]=(w2,w2,w3,w3), tap=(ci*K+kh)*K+kw
__constant__ ulonglong2 c_w5d[200];
__constant__ ulonglong2 c_w3d[72];
__device__ float4 g_wpack[272];

template <int K>
__device__ __forceinline__ ulonglong2 cwload(int i);
template <>
__device__ __forceinline__ ulonglong2 cwload<5>(int i) { return c_w5d[i]; }
template <>
__device__ __forceinline__ ulonglong2 cwload<3>(int i) { return c_w3d[i]; }

__device__ __forceinline__ void fma2(u64& d, u64 a, u64 b) {
    asm("fma.rn.f32x2 %0, %1, %2, %0;" : "+l"(d) : "l"(a), "l"(b));
}
__device__ __forceinline__ float2 upk(u64 v) {
    float2 f;
    f.x = __uint_as_float((unsigned)(v & 0xffffffffull));
    f.y = __uint_as_float((unsigned)(v >> 32));
    return f;
}

__global__ void repack_kernel(const float* __restrict__ w1,
                              const float* __restrict__ w2) {
    int tid = threadIdx.x;
    if (tid < 100) {
        float a = w1[tid], b = w1[100 + tid], c = w1[200 + tid], d = w1[300 + tid];
        g_wpack[tid * 2 + 0] = make_float4(a, a, b, b);
        g_wpack[tid * 2 + 1] = make_float4(c, c, d, d);
    }
    if (tid >= 128 && tid < 164) {
        int t = tid - 128;
        float a = w2[t], b = w2[36 + t], c = w2[72 + t], d = w2[108 + t];
        g_wpack[200 + t * 2 + 0] = make_float4(a, a, b, b);
        g_wpack[200 + t * 2 + 1] = make_float4(c, c, d, d);
    }
}

// ---------------------------------------------------------------------------
// Standalone alpha-PSP (layer 1). Warp-local smem transpose. (39us, near-roof)
// ---------------------------------------------------------------------------
#define PW_PAD 53
#define PW_WARPS 8
#define PW_SMEM (PW_WARPS * 32 * PW_PAD * 4)

__global__ void __launch_bounds__(256, 4) psp_kernel(const float* __restrict__ in,
                                                     float* __restrict__ out,
                                                     float r, float coef) {
    extern __shared__ float sm[];
    const int lane = threadIdx.x & 31;
    const int wrp  = threadIdx.x >> 5;
    float* ws = sm + wrp * 32 * PW_PAD;
    const long base = (long)(blockIdx.x * (PW_WARPS * 32) + wrp * 32) * TT;
    const float* g = in + base;
#pragma unroll
    for (int w = 0; w < 32; ++w) {
        ws[w * PW_PAD + lane] = g[w * TT + lane];
        if (lane < TT - 32) ws[w * PW_PAD + 32 + lane] = g[w * TT + 32 + lane];
    }
    __syncwarp();
    float* row = ws + lane * PW_PAD;
    float s1 = 0.f, s2 = 0.f;
#pragma unroll
    for (int t = 0; t < TT; ++t) {
        float x = row[t];
        row[t] = coef * s2;
        s1 = fmaf(r, s1, x);
        s2 = fmaf(r, s2, r * s1);
    }
    __syncwarp();
    float* o = out + base;
#pragma unroll
    for (int w = 0; w < 32; ++w) {
        o[w * TT + lane] = ws[w * PW_PAD + lane];
        if (lane < TT - 32) o[w * TT + 32 + lane] = ws[w * PW_PAD + 32 + lane];
    }
}

// ---------------------------------------------------------------------------
// Fused conv(KxK, 4->4, pad K/2) + spike epilogue, double-buffered over ci.
// Block (32w, h, n), 416 thr = 13 warps, thread = (w=lane, t-quad t0=4*wrp).
// Round i: compute ci=i from stage i%2 while filling ci=i+1 into the other
// stage (fill LDG latency hidden under FMA work). Fill is straight-line
// float2 copies (rows wrp, wrp+13, wrp+26), fully unrolled -> high MLP.
// ---------------------------------------------------------------------------
template <int K, int EPI>
__global__ void __launch_bounds__(416, 3)
conv_fused_kernel(const float* __restrict__ in, float* __restrict__ out,
                  float rR, float cR, float theta, float rP, float cP) {
    constexpr int PAD   = K / 2;
    constexpr int WH    = 32 + 2 * PAD;
    constexpr int STAGE = K * WH * TP;   // floats per stage

    extern __shared__ float sm[];

    const int tid  = threadIdx.x;
    const int lane = tid & 31;
    const int wrp  = tid >> 5;
    const int w0   = blockIdx.x * 32;
    const int h    = blockIdx.y;
    const int n    = blockIdx.z;
    const int t0   = wrp * 4;

    // ---- fill one stage with channel ci (straight-line, float2) ----
    auto fill = [&](int buf, int ci) {
        if (lane >= 25) return;
        float2* dstb = reinterpret_cast<float2*>(sm + buf * STAGE);
#pragma unroll
        for (int kh = 0; kh < K; ++kh) {
            const int hh  = h + kh - PAD;
            const bool hok = (hh >= 0) && (hh < HHT);
            const float* srcf = in + (((long)(n * CHN + ci) * HHT + hh) * WWD + (w0 - PAD)) * TT;
            const float2* src2 = reinterpret_cast<const float2*>(srcf);
            float2* dst2 = dstb + kh * WH * (TP / 2);
#pragma unroll
            for (int rr = 0; rr < 3; ++rr) {
                const int row = wrp + rr * 13;
                if (row < WH) {
                    const int wg = w0 - PAD + row;
                    float2 v = make_float2(0.f, 0.f);
                    if (hok && wg >= 0 && wg < WWD) v = src2[row * (TT / 2) + lane];
                    dst2[row * (TP / 2) + lane] = v;
                }
            }
        }
    };

    u64 acc[4][2];   // [co][(t0,t0+1)|(t0+2,t0+3)]
#pragma unroll
    for (int c = 0; c < 4; ++c) { acc[c][0] = 0ull; acc[c][1] = 0ull; }

    fill(0, 0);
    __syncthreads();

#pragma unroll
    for (int ci = 0; ci < CHN; ++ci) {
        const float* s_in = sm + (ci & 1) * STAGE;
        // compute first (post-barrier everyone has FMA work immediately)
#pragma unroll
        for (int kh = 0; kh < K; ++kh) {
            const float* rowp = s_in + (kh * WH + lane) * TP + t0;
#pragma unroll
            for (int kw = 0; kw < K; ++kw) {
                const int tap = (ci * K + kh) * K + kw;
                const ulonglong2 iv = *reinterpret_cast<const ulonglong2*>(rowp + kw * TP);
                const ulonglong2 wa = cwload<K>(tap * 2);
                const ulonglong2 wb = cwload<K>(tap * 2 + 1);
                fma2(acc[0][0], iv.x, wa.x);
                fma2(acc[0][1], iv.y, wa.x);
                fma2(acc[1][0], iv.x, wa.y);
                fma2(acc[1][1], iv.y, wa.y);
                fma2(acc[2][0], iv.x, wb.x);
                fma2(acc[2][1], iv.y, wb.x);
                fma2(acc[3][0], iv.x, wb.y);
                fma2(acc[3][1], iv.y, wb.y);
            }
        }
        // then stream next channel into the other stage
        if (ci < CHN - 1) fill((ci + 1) & 1, ci + 1);
        __syncthreads();
    }

    // stage conv results: s_out[co][w][SOP], float2 stores
    float* s_out = sm;   // overlay: 4*32*52*4 = 26.6KB < 2*STAGE
#pragma unroll
    for (int co = 0; co < 4; ++co) {
        float* p = s_out + (co * 32 + lane) * SOP + t0;
        float2 a = upk(acc[co][0]);
        *reinterpret_cast<float2*>(p) = a;
        if (t0 + 2 < TT) {
            float2 b = upk(acc[co][1]);
            *reinterpret_cast<float2*>(p + 2) = b;
        }
    }
    __syncthreads();

    // fused spike-dynamics epilogue: 128 pixels (4co x 32w)
    if (tid < 128) {
        const int co = tid >> 5;
        const int w  = tid & 31;
        float* row = s_out + (co * 32 + w) * SOP;
        float sd1 = 0.f, sd2 = 0.f, sp1 = 0.f, sp2 = 0.f;
#pragma unroll
        for (int t = 0; t < TT; ++t) {
            float m = fmaf(cR, sd2, row[t]);
            float s = (m >= theta) ? 1.f : 0.f;
            sd1 = fmaf(rR, sd1, s);
            sd2 = fmaf(rR, sd2, rR * sd1);
            if (EPI == 0) {
                row[t] = cP * sp2;
                sp1 = fmaf(rP, sp1, s);
                sp2 = fmaf(rP, sp2, rP * sp1);
            } else {
                row[t] = s;
            }
        }
    }
    __syncthreads();

    // structured coalesced store: float2, warp-per-w-row
    if (lane < 25) {
#pragma unroll
        for (int co = 0; co < 4; ++co) {
            const float2* s2 = reinterpret_cast<const float2*>(s_out + co * 32 * SOP);
            float2* g2 = reinterpret_cast<float2*>(
                out + (((long)(n * CHN + co) * HHT + h) * WWD + w0) * TT);
#pragma unroll
            for (int rr = 0; rr < 3; ++rr) {
                const int w = wrp + rr * 13;
                if (w < 32) g2[w * (TT / 2) + lane] = s2[w * (SOP / 2) + lane];
            }
        }
    }
}

// ---------------------------------------------------------------------------

extern "C" void kernel_launch(void* const* d_in, const int* in_sizes, int n_in,
                              void* d_out, int out_size) {
    const float* x  = (const float*)d_in[0];
    const float* w1 = (const float*)d_in[1];
    const float* w2 = (const float*)d_in[2];
    float* outp = (float*)d_out;

    float *bufA, *bufB;
    cudaGetSymbolAddress((void**)&bufA, g_bufA);
    cudaGetSymbolAddress((void**)&bufB, g_bufB);
    float4* wpack;
    cudaGetSymbolAddress((void**)&wpack, g_wpack);

    const int SMEM5 = 2 * 5 * 36 * TP * 4;   // 74880 B -> 3 blocks/SM
    const int SMEM3 = 2 * 3 * 34 * TP * 4;   // 42432 B -> 3 blocks/SM
    cudaFuncSetAttribute((const void*)conv_fused_kernel<5, 0>,
                         cudaFuncAttributeMaxDynamicSharedMemorySize, SMEM5);
    cudaFuncSetAttribute((const void*)conv_fused_kernel<3, 1>,
                         cudaFuncAttributeMaxDynamicSharedMemorySize, SMEM3);
    cudaFuncSetAttribute((const void*)psp_kernel,
                         cudaFuncAttributeMaxDynamicSharedMemorySize, PW_SMEM);

    const float r1  = (float)0.36787944117144233;   // exp(-1/tau1)
    const float cP1 = (float)2.718281828459045;     // e/tau1
    const float rR1 = (float)0.36787944117144233;   // exp(-1/tauRef1)
    const float cR1 = (float)(-54.365636569180902); // -scaleRef*theta1*e/tauRef1
    const float th1 = 20.0f;
    const float r2  = (float)0.6065306597126334;    // exp(-1/tau2)
    const float cP2 = (float)1.3591409142295225;    // e/tau2
    const float rR2 = (float)0.6065306597126334;    // exp(-1/tauRef2)
    const float cR2 = (float)(-54.365636569180902); // -scaleRef*theta2*e/tauRef2
    const float th2 = 40.0f;

    const int PGRID = NPIX / (PW_WARPS * 32);   // 2048
    dim3 cgrid(WWD / 32, HHT, NBATCH);          // (4,128,8)

    repack_kernel<<<1, 256>>>(w1, w2);
    cudaMemcpyToSymbolAsync(c_w5d, wpack, 200 * sizeof(float4), 0,
                            cudaMemcpyDeviceToDevice, 0);
    cudaMemcpyToSymbolAsync(c_w3d, wpack + 200, 72 * sizeof(float4), 0,
                            cudaMemcpyDeviceToDevice, 0);

    psp_kernel<<<PGRID, 256, PW_SMEM>>>(x, bufA, r1, cP1);
    conv_fused_kernel<5, 0><<<cgrid, 416, SMEM5>>>(bufA, bufB,
                                                   rR1, cR1, th1, r2, cP2);
    conv_fused_kernel<3, 1><<<cgrid, 416, SMEM3>>>(bufB, outp,
                                                   rR2, cR2, th2, 0.f, 0.f);
}

// round 10
// speedup vs baseline: 1.5124x; 1.2883x over previous
#include <cuda_runtime.h>

#define CHN   4
#define HHT   128
#define WWD   128
#define TT    50
#define TP    52          // padded t-stride: mult of 4 (LDS.128), conflict-free
#define SOP   52          // staging row stride (floats), float2 aligned
#define NBATCH 8
#define NPIX  (NBATCH*CHN*HHT*WWD)
#define NELEM (NPIX*TT)

__device__ float g_bufA[NELEM];
__device__ float g_bufB[NELEM];

typedef unsigned long long u64;

// Pre-duplicated weights in constant memory.
// c_w5d[tap*2+0]=(w0,w0,w1,w1), [tap*2+1]=(w2,w2,w3,w3), tap=(ci*K+kh)*K+kw
__constant__ ulonglong2 c_w5d[200];
__constant__ ulonglong2 c_w3d[72];
__device__ float4 g_wpack[272];

template <int K>
__device__ __forceinline__ ulonglong2 cwload(int i);
template <>
__device__ __forceinline__ ulonglong2 cwload<5>(int i) { return c_w5d[i]; }
template <>
__device__ __forceinline__ ulonglong2 cwload<3>(int i) { return c_w3d[i]; }

__device__ __forceinline__ void fma2(u64& d, u64 a, u64 b) {
    asm("fma.rn.f32x2 %0, %1, %2, %0;" : "+l"(d) : "l"(a), "l"(b));
}
__device__ __forceinline__ float2 upk(u64 v) {
    float2 f;
    f.x = __uint_as_float((unsigned)(v & 0xffffffffull));
    f.y = __uint_as_float((unsigned)(v >> 32));
    return f;
}

__global__ void repack_kernel(const float* __restrict__ w1,
                              const float* __restrict__ w2) {
    int tid = threadIdx.x;
    if (tid < 100) {
        float a = w1[tid], b = w1[100 + tid], c = w1[200 + tid], d = w1[300 + tid];
        g_wpack[tid * 2 + 0] = make_float4(a, a, b, b);
        g_wpack[tid * 2 + 1] = make_float4(c, c, d, d);
    }
    if (tid >= 128 && tid < 164) {
        int t = tid - 128;
        float a = w2[t], b = w2[36 + t], c = w2[72 + t], d = w2[108 + t];
        g_wpack[200 + t * 2 + 0] = make_float4(a, a, b, b);
        g_wpack[200 + t * 2 + 1] = make_float4(c, c, d, d);
    }
}

// ---------------------------------------------------------------------------
// Standalone alpha-PSP (layer 1). Warp-local smem transpose. (39us, near-roof)
// ---------------------------------------------------------------------------
#define PW_PAD 53
#define PW_WARPS 8
#define PW_SMEM (PW_WARPS * 32 * PW_PAD * 4)

__global__ void __launch_bounds__(256, 4) psp_kernel(const float* __restrict__ in,
                                                     float* __restrict__ out,
                                                     float r, float coef) {
    extern __shared__ float sm[];
    const int lane = threadIdx.x & 31;
    const int wrp  = threadIdx.x >> 5;
    float* ws = sm + wrp * 32 * PW_PAD;
    const long base = (long)(blockIdx.x * (PW_WARPS * 32) + wrp * 32) * TT;
    const float* g = in + base;
#pragma unroll
    for (int w = 0; w < 32; ++w) {
        ws[w * PW_PAD + lane] = g[w * TT + lane];
        if (lane < TT - 32) ws[w * PW_PAD + 32 + lane] = g[w * TT + 32 + lane];
    }
    __syncwarp();
    float* row = ws + lane * PW_PAD;
    float s1 = 0.f, s2 = 0.f;
#pragma unroll
    for (int t = 0; t < TT; ++t) {
        float x = row[t];
        row[t] = coef * s2;
        s1 = fmaf(r, s1, x);
        s2 = fmaf(r, s2, r * s1);
    }
    __syncwarp();
    float* o = out + base;
#pragma unroll
    for (int w = 0; w < 32; ++w) {
        o[w * TT + lane] = ws[w * PW_PAD + lane];
        if (lane < TT - 32) o[w * TT + 32 + lane] = ws[w * PW_PAD + 32 + lane];
    }
}

// ---------------------------------------------------------------------------
// Fused conv(KxK, 4->4, pad K/2) + spike epilogue, cp.async double-buffered.
// Block (32w, h, n), 416 thr = 13 warps, thread = (w=lane, t-quad t0=4*wrp).
// Stage ci+1 streams into the idle buffer via cp.async (no register round
// trip) WHILE stage ci is computed; wait_group+barrier after the compute.
// Per tap: 1 LDS.128 input + 2 LDC.128 duplicated weights + 8 FFMA2.
// ---------------------------------------------------------------------------
template <int K, int EPI>
__global__ void __launch_bounds__(416, 3)
conv_fused_kernel(const float* __restrict__ in, float* __restrict__ out,
                  float rR, float cR, float theta, float rP, float cP) {
    constexpr int PAD   = K / 2;
    constexpr int WH    = 32 + 2 * PAD;
    constexpr int STAGE = K * WH * TP;   // floats per stage

    extern __shared__ float sm[];
    const unsigned smem_base = (unsigned)__cvta_generic_to_shared(sm);

    const int tid  = threadIdx.x;
    const int lane = tid & 31;
    const int wrp  = tid >> 5;
    const int w0   = blockIdx.x * 32;
    const int h    = blockIdx.y;
    const int n    = blockIdx.z;
    const int t0   = wrp * 4;

    // async fill of one stage with channel ci: 8B cp.async per (kh,row,lane<25)
    auto fill = [&](int buf, int ci) {
        if (lane < 25) {
            const unsigned dstb = smem_base + buf * (STAGE * 4) + lane * 8;
#pragma unroll
            for (int kh = 0; kh < K; ++kh) {
                const int hh  = h + kh - PAD;
                const bool hok = (hh >= 0) && (hh < HHT);
                const char* srcb = (const char*)(in +
                    (((long)(n * CHN + ci) * HHT + hh) * WWD + (w0 - PAD)) * TT);
#pragma unroll
                for (int rr = 0; rr < 3; ++rr) {
                    const int row = wrp + rr * 13;
                    if (row < WH) {
                        const int wg = w0 - PAD + row;
                        const bool ok = hok && (wg >= 0) && (wg < WWD);
                        const void* src = ok ? (const void*)(srcb + row * (TT * 4) + lane * 8)
                                             : (const void*)in;   // clamped, never read
                        const int sz = ok ? 8 : 0;                // 0 -> zero-fill
                        const unsigned dst = dstb + (kh * WH + row) * (TP * 4);
                        asm volatile("cp.async.ca.shared.global [%0], [%1], 8, %2;"
                                     :: "r"(dst), "l"(src), "r"(sz) : "memory");
                    }
                }
            }
        }
        asm volatile("cp.async.commit_group;" ::: "memory");
    };

    u64 acc[4][2];   // [co][(t0,t0+1)|(t0+2,t0+3)]
#pragma unroll
    for (int c = 0; c < 4; ++c) { acc[c][0] = 0ull; acc[c][1] = 0ull; }

    fill(0, 0);
    asm volatile("cp.async.wait_group 0;" ::: "memory");
    __syncthreads();

#pragma unroll
    for (int ci = 0; ci < CHN; ++ci) {
        // launch next stage's fill first: latency overlaps this stage's FMAs
        if (ci < CHN - 1) fill((ci + 1) & 1, ci + 1);
        const float* s_in = sm + (ci & 1) * STAGE;
#pragma unroll
        for (int kh = 0; kh < K; ++kh) {
            const float* rowp = s_in + (kh * WH + lane) * TP + t0;
#pragma unroll
            for (int kw = 0; kw < K; ++kw) {
                const int tap = (ci * K + kh) * K + kw;
                const ulonglong2 iv = *reinterpret_cast<const ulonglong2*>(rowp + kw * TP);
                const ulonglong2 wa = cwload<K>(tap * 2);
                const ulonglong2 wb = cwload<K>(tap * 2 + 1);
                fma2(acc[0][0], iv.x, wa.x);
                fma2(acc[0][1], iv.y, wa.x);
                fma2(acc[1][0], iv.x, wa.y);
                fma2(acc[1][1], iv.y, wa.y);
                fma2(acc[2][0], iv.x, wb.x);
                fma2(acc[2][1], iv.y, wb.x);
                fma2(acc[3][0], iv.x, wb.y);
                fma2(acc[3][1], iv.y, wb.y);
            }
        }
        if (ci < CHN - 1) {
            asm volatile("cp.async.wait_group 0;" ::: "memory");
            __syncthreads();
        }
    }
    __syncthreads();

    // stage conv results: s_out[co][w][SOP], float2 stores
    float* s_out = sm;   // overlay: 4*32*52*4 = 26.6KB < 2*STAGE
#pragma unroll
    for (int co = 0; co < 4; ++co) {
        float* p = s_out + (co * 32 + lane) * SOP + t0;
        float2 a = upk(acc[co][0]);
        *reinterpret_cast<float2*>(p) = a;
        if (t0 + 2 < TT) {
            float2 b = upk(acc[co][1]);
            *reinterpret_cast<float2*>(p + 2) = b;
        }
    }
    __syncthreads();

    // fused spike-dynamics epilogue: 128 pixels (4co x 32w)
    if (tid < 128) {
        const int co = tid >> 5;
        const int w  = tid & 31;
        float* row = s_out + (co * 32 + w) * SOP;
        float sd1 = 0.f, sd2 = 0.f, sp1 = 0.f, sp2 = 0.f;
#pragma unroll
        for (int t = 0; t < TT; ++t) {
            float m = fmaf(cR, sd2, row[t]);
            float s = (m >= theta) ? 1.f : 0.f;
            sd1 = fmaf(rR, sd1, s);
            sd2 = fmaf(rR, sd2, rR * sd1);
            if (EPI == 0) {
                row[t] = cP * sp2;
                sp1 = fmaf(rP, sp1, s);
                sp2 = fmaf(rP, sp2, rP * sp1);
            } else {
                row[t] = s;
            }
        }
    }
    __syncthreads();

    // structured coalesced store: float2, warp-per-w-row
    if (lane < 25) {
#pragma unroll
        for (int co = 0; co < 4; ++co) {
            const float2* s2 = reinterpret_cast<const float2*>(s_out + co * 32 * SOP);
            float2* g2 = reinterpret_cast<float2*>(
                out + (((long)(n * CHN + co) * HHT + h) * WWD + w0) * TT);
#pragma unroll
            for (int rr = 0; rr < 3; ++rr) {
                const int w = wrp + rr * 13;
                if (w < 32) g2[w * (TT / 2) + lane] = s2[w * (SOP / 2) + lane];
            }
        }
    }
}

// ---------------------------------------------------------------------------

extern "C" void kernel_launch(void* const* d_in, const int* in_sizes, int n_in,
                              void* d_out, int out_size) {
    const float* x  = (const float*)d_in[0];
    const float* w1 = (const float*)d_in[1];
    const float* w2 = (const float*)d_in[2];
    float* outp = (float*)d_out;

    float *bufA, *bufB;
    cudaGetSymbolAddress((void**)&bufA, g_bufA);
    cudaGetSymbolAddress((void**)&bufB, g_bufB);
    float4* wpack;
    cudaGetSymbolAddress((void**)&wpack, g_wpack);

    const int SMEM5 = 2 * 5 * 36 * TP * 4;   // 74880 B -> 3 blocks/SM
    const int SMEM3 = 2 * 3 * 34 * TP * 4;   // 42432 B -> 3 blocks/SM
    cudaFuncSetAttribute((const void*)conv_fused_kernel<5, 0>,
                         cudaFuncAttributeMaxDynamicSharedMemorySize, SMEM5);
    cudaFuncSetAttribute((const void*)conv_fused_kernel<3, 1>,
                         cudaFuncAttributeMaxDynamicSharedMemorySize, SMEM3);
    cudaFuncSetAttribute((const void*)psp_kernel,
                         cudaFuncAttributeMaxDynamicSharedMemorySize, PW_SMEM);

    const float r1  = (float)0.36787944117144233;   // exp(-1/tau1)
    const float cP1 = (float)2.718281828459045;     // e/tau1
    const float rR1 = (float)0.36787944117144233;   // exp(-1/tauRef1)
    const float cR1 = (float)(-54.365636569180902); // -scaleRef*theta1*e/tauRef1
    const float th1 = 20.0f;
    const float r2  = (float)0.6065306597126334;    // exp(-1/tau2)
    const float cP2 = (float)1.3591409142295225;    // e/tau2
    const float rR2 = (float)0.6065306597126334;    // exp(-1/tauRef2)
    const float cR2 = (float)(-54.365636569180902); // -scaleRef*theta2*e/tauRef2
    const float th2 = 40.0f;

    const int PGRID = NPIX / (PW_WARPS * 32);   // 2048
    dim3 cgrid(WWD / 32, HHT, NBATCH);          // (4,128,8)

    repack_kernel<<<1, 256>>>(w1, w2);
    cudaMemcpyToSymbolAsync(c_w5d, wpack, 200 * sizeof(float4), 0,
                            cudaMemcpyDeviceToDevice, 0);
    cudaMemcpyToSymbolAsync(c_w3d, wpack + 200, 72 * sizeof(float4), 0,
                            cudaMemcpyDeviceToDevice, 0);

    psp_kernel<<<PGRID, 256, PW_SMEM>>>(x, bufA, r1, cP1);
    conv_fused_kernel<5, 0><<<cgrid, 416, SMEM5>>>(bufA, bufB,
                                                   rR1, cR1, th1, r2, cP2);
    conv_fused_kernel<3, 1><<<cgrid, 416, SMEM3>>>(bufB, outp,
                                                   rR2, cR2, th2, 0.f, 0.f);
}